// round 10
// baseline (speedup 1.0000x reference)
#include <cuda_runtime.h>
#include <stdint.h>

// VolGeoNet trilinear interp: Morton cell-sorted points + static-range warps.
// - Points counting-sorted by 18-bit Morton cell key (64^3 cells, ~1 pt/cell):
//   consecutive points are spatially adjacent -> warp L1 working set ~8-30KB.
// - Main kernel: each warp owns a contiguous slice of the sorted array and
//   computes the FULL 256-channel output per point (no channel-half split,
//   no bins, no work stealing). 1480 CTAs x 128 thr, <=51 regs, 40 warps/SM.
// Inputs: x [B,3] f32, grid_value [65^3,1] f32, grid_feature [65^3,256] f32.
// Output: concat(out [B,1], feat [B,256]) float, out first.

#define N1 65
#define W_FEAT 256
#define MAXB 262144
#define NKEYS (64 * 64 * 64)      // 262144 cells
#define SCAN_BLOCKS 256           // NKEYS / 1024
#define GRID_MAIN 1480            // 10 CTAs/SM x 148
#define WARPS_MAIN (GRID_MAIN * 4)

__device__ int    g_hist[NKEYS];      // zero at entry every call (scan1 resets)
__device__ int    g_binloc[NKEYS];    // block-local exclusive prefix
__device__ int    g_bsum[SCAN_BLOCKS];
__device__ int    g_bsumx[SCAN_BLOCKS];
__device__ int    g_key[MAXB];
__device__ int    g_rank[MAXB];
__device__ float4 g_xs[MAXB];         // sorted (x,y,z, bitcast point-index)

__device__ __forceinline__ uint32_t part1by2(uint32_t v)
{
    v &= 0x3FF;
    v = (v | (v << 16)) & 0x030000FF;
    v = (v | (v <<  8)) & 0x0300F00F;
    v = (v | (v <<  4)) & 0x030C30C3;
    v = (v | (v <<  2)) & 0x09249249;
    return v;
}

__global__ void histo_kernel(const float* __restrict__ x, int B)
{
    int p = blockIdx.x * blockDim.x + threadIdx.x;
    if (p >= B) return;
    const float rx = (x[p * 3 + 0] + 1.0f) * 32.0f;
    const float ry = (x[p * 3 + 1] + 1.0f) * 32.0f;
    const float rz = (x[p * 3 + 2] + 1.0f) * 32.0f;
    int ix = (int)floorf(rx); ix = ix < 0 ? 0 : (ix > 63 ? 63 : ix);
    int iy = (int)floorf(ry); iy = iy < 0 ? 0 : (iy > 63 ? 63 : iy);
    int iz = (int)floorf(rz); iz = iz < 0 ? 0 : (iz > 63 ? 63 : iz);
    const int key = (int)((part1by2(ix) << 2) | (part1by2(iy) << 1) | part1by2(iz));
    g_key[p] = key;
    g_rank[p] = atomicAdd(&g_hist[key], 1);
}

// Block-local exclusive scan over 1024 bins; emits block totals; resets g_hist.
__global__ void __launch_bounds__(1024) scan1_kernel()
{
    __shared__ int s[1024];
    const int t = threadIdx.x;
    const int idx = blockIdx.x * 1024 + t;
    const int v = g_hist[idx];
    s[t] = v;
    __syncthreads();
    for (int off = 1; off < 1024; off <<= 1) {
        int a = 0;
        if (t >= off) a = s[t - off];
        __syncthreads();
        if (t >= off) s[t] += a;
        __syncthreads();
    }
    g_binloc[idx] = s[t] - v;                 // exclusive
    if (t == 1023) g_bsum[blockIdx.x] = s[t]; // block total
    g_hist[idx] = 0;                          // reset for next launch call
}

// Exclusive scan of the 256 block totals.
__global__ void __launch_bounds__(SCAN_BLOCKS) scan2_kernel()
{
    __shared__ int s[SCAN_BLOCKS];
    const int t = threadIdx.x;
    const int v = g_bsum[t];
    s[t] = v;
    __syncthreads();
    for (int off = 1; off < SCAN_BLOCKS; off <<= 1) {
        int a = 0;
        if (t >= off) a = s[t - off];
        __syncthreads();
        if (t >= off) s[t] += a;
        __syncthreads();
    }
    g_bsumx[t] = s[t] - v;
}

__global__ void scatter_kernel(const float* __restrict__ x, int B)
{
    int p = blockIdx.x * blockDim.x + threadIdx.x;
    if (p >= B) return;
    const int key = g_key[p];
    const int dst = g_binloc[key] + g_bsumx[key >> 10] + g_rank[p];
    g_xs[dst] = make_float4(x[p * 3 + 0], x[p * 3 + 1], x[p * 3 + 2],
                            __int_as_float(p));
}

// ──────────────────────────────────────────────────────────────────────────
// Main kernel: warp w owns sorted indices [w*ppw, (w+1)*ppw). Full 256
// channels per point: lane handles float4 columns lane and lane+32.
__global__ void __launch_bounds__(128, 10) trilerp_main_kernel(
    const float* __restrict__ gv,
    const float* __restrict__ gf,
    float* __restrict__ out_val,   // [B]
    float* __restrict__ out_feat,  // [B, 256]
    int B, int ppw)
{
    const int wid  = threadIdx.x >> 5;
    const int lane = threadIdx.x & 31;
    const int w = blockIdx.x * 4 + wid;

    int i = w * ppw;
    int iend = i + ppw;
    if (iend > B) iend = B;

    for (; i < iend; i++) {
        const float4 xp = __ldg(&g_xs[i]);     // warp-broadcast
        const int p = __float_as_int(xp.w);

        const float rx = (xp.x + 1.0f) * 32.0f;
        const float ry = (xp.y + 1.0f) * 32.0f;
        const float rz = (xp.z + 1.0f) * 32.0f;

        const bool valid = (rx >= 0.0f) && (rx <= 64.0f) &&
                           (ry >= 0.0f) && (ry <= 64.0f) &&
                           (rz >= 0.0f) && (rz <= 64.0f);
        const float vmask = valid ? 1.0f : 0.0f;

        int ix = (int)floorf(rx); ix = ix < 0 ? 0 : (ix > 63 ? 63 : ix);
        int iy = (int)floorf(ry); iy = iy < 0 ? 0 : (iy > 63 ? 63 : iy);
        int iz = (int)floorf(rz); iz = iz < 0 ? 0 : (iz > 63 ? 63 : iz);

        const float tx = rx - (float)ix;
        const float ty = ry - (float)iy;
        const float tz = rz - (float)iz;
        const float wx0 = 1.0f - tx, wy0 = 1.0f - ty, wz0 = 1.0f - tz;

        const float wyz0 = wy0 * wz0;
        const float wyz1 = wy0 * tz;
        const float wyz2 = ty  * wz0;
        const float wyz3 = ty  * tz;

        const int base = (ix * N1 + iy) * N1 + iz;
        const float4* r = (const float4*)gf + (size_t)base * (W_FEAT / 4) + lane;
        float4* frow = (float4*)(out_feat + (size_t)p * W_FEAT);

#pragma unroll
        for (int h = 0; h < 2; h++) {
            const float4* rh = r + h * 32;

            // x-low plane: (0,0,0),(0,0,1),(0,1,0),(0,1,1)
            const float4 f0 = __ldg(rh);
            const float4 f1 = __ldg(rh + (W_FEAT / 4));
            const float4 f2 = __ldg(rh + N1 * (W_FEAT / 4));
            const float4 f3 = __ldg(rh + (N1 + 1) * (W_FEAT / 4));
            float s0, s1, s2, s3;
            s0 = wyz0 * f0.x; s1 = wyz0 * f0.y; s2 = wyz0 * f0.z; s3 = wyz0 * f0.w;
            s0 = fmaf(wyz1, f1.x, s0); s1 = fmaf(wyz1, f1.y, s1);
            s2 = fmaf(wyz1, f1.z, s2); s3 = fmaf(wyz1, f1.w, s3);
            s0 = fmaf(wyz2, f2.x, s0); s1 = fmaf(wyz2, f2.y, s1);
            s2 = fmaf(wyz2, f2.z, s2); s3 = fmaf(wyz2, f2.w, s3);
            s0 = fmaf(wyz3, f3.x, s0); s1 = fmaf(wyz3, f3.y, s1);
            s2 = fmaf(wyz3, f3.z, s2); s3 = fmaf(wyz3, f3.w, s3);
            s0 *= wx0; s1 *= wx0; s2 *= wx0; s3 *= wx0;

            // x-high plane
            const float4* rhx = rh + N1 * N1 * (W_FEAT / 4);
            const float4 g0 = __ldg(rhx);
            const float4 g1 = __ldg(rhx + (W_FEAT / 4));
            const float4 g2 = __ldg(rhx + N1 * (W_FEAT / 4));
            const float4 g3 = __ldg(rhx + (N1 + 1) * (W_FEAT / 4));
            float u0, u1, u2, u3;
            u0 = wyz0 * g0.x; u1 = wyz0 * g0.y; u2 = wyz0 * g0.z; u3 = wyz0 * g0.w;
            u0 = fmaf(wyz1, g1.x, u0); u1 = fmaf(wyz1, g1.y, u1);
            u2 = fmaf(wyz1, g1.z, u2); u3 = fmaf(wyz1, g1.w, u3);
            u0 = fmaf(wyz2, g2.x, u0); u1 = fmaf(wyz2, g2.y, u1);
            u2 = fmaf(wyz2, g2.z, u2); u3 = fmaf(wyz2, g2.w, u3);
            u0 = fmaf(wyz3, g3.x, u0); u1 = fmaf(wyz3, g3.y, u1);
            u2 = fmaf(wyz3, g3.z, u2); u3 = fmaf(wyz3, g3.w, u3);

            s0 = fmaf(tx, u0, s0); s1 = fmaf(tx, u1, s1);
            s2 = fmaf(tx, u2, s2); s3 = fmaf(tx, u3, s3);

            __stcs(frow + h * 32 + lane,
                   make_float4(s0 * vmask, s1 * vmask, s2 * vmask, s3 * vmask));
        }

        // grid_value: lanes 0..7 own one corner (bit2=ox, bit1=oy, bit0=oz).
        {
            const float wxs = (lane & 4) ? tx : wx0;
            const float wys = (lane & 2) ? ty : wy0;
            const float wzs = (lane & 1) ? tz : wz0;
            const int off = ((lane & 4) ? N1 * N1 : 0) +
                            ((lane & 2) ? N1 : 0) + (lane & 1);
            float gvv = 0.0f;
            if (lane < 8) gvv = wxs * wys * wzs * __ldg(gv + base + off);
            gvv += __shfl_xor_sync(0xffffffffu, gvv, 4);
            gvv += __shfl_xor_sync(0xffffffffu, gvv, 2);
            gvv += __shfl_xor_sync(0xffffffffu, gvv, 1);
            if (lane == 0) out_val[p] = gvv * vmask;
        }
    }
}

// Fallback (B > MAXB): direct global-gather version, unsorted.
__global__ void __launch_bounds__(256) trilerp_kernel(
    const float* __restrict__ x,
    const float* __restrict__ gv,
    const float* __restrict__ gf,
    float* __restrict__ out_val,
    float* __restrict__ out_feat,
    int B)
{
    const int p = (blockIdx.x * blockDim.x + threadIdx.x) >> 5;
    const int lane = threadIdx.x & 31;
    if (p >= B) return;

    const float rx = (__ldg(x + p * 3 + 0) + 1.0f) * 32.0f;
    const float ry = (__ldg(x + p * 3 + 1) + 1.0f) * 32.0f;
    const float rz = (__ldg(x + p * 3 + 2) + 1.0f) * 32.0f;
    const bool valid = (rx >= 0.0f) && (rx <= 64.0f) && (ry >= 0.0f) &&
                       (ry <= 64.0f) && (rz >= 0.0f) && (rz <= 64.0f);
    const float vmask = valid ? 1.0f : 0.0f;
    int ix = (int)floorf(rx); ix = ix < 0 ? 0 : (ix > 63 ? 63 : ix);
    int iy = (int)floorf(ry); iy = iy < 0 ? 0 : (iy > 63 ? 63 : iy);
    int iz = (int)floorf(rz); iz = iz < 0 ? 0 : (iz > 63 ? 63 : iz);
    const float tx = rx - ix, ty = ry - iy, tz = rz - iz;
    const int base = (ix * N1 + iy) * N1 + iz;
    const float wx0 = 1.0f - tx, wy0 = 1.0f - ty, wz0 = 1.0f - tz;
    float w[8] = { wx0*wy0*wz0, wx0*wy0*tz, wx0*ty*wz0, wx0*ty*tz,
                   tx*wy0*wz0,  tx*wy0*tz,  tx*ty*wz0,  tx*ty*tz };
    const int offs[8] = { 0, 1, N1, N1+1, N1*N1, N1*N1+1, N1*N1+N1, N1*N1+N1+1 };

    float gvv = 0.0f;
    if (lane < 8) gvv = w[lane] * __ldg(gv + base + offs[lane]);
    gvv += __shfl_xor_sync(0xffffffffu, gvv, 4);
    gvv += __shfl_xor_sync(0xffffffffu, gvv, 2);
    gvv += __shfl_xor_sync(0xffffffffu, gvv, 1);
    if (lane == 0) out_val[p] = gvv * vmask;

    float a0=0,a1=0,a2=0,a3=0,b0=0,b1=0,b2=0,b3=0;
#pragma unroll
    for (int c = 0; c < 8; c++) {
        const float4* row = (const float4*)(gf + (size_t)(base + offs[c]) * W_FEAT);
        const float4 fa = __ldg(row + lane);
        const float4 fb = __ldg(row + lane + 32);
        const float wc = w[c];
        a0 = fmaf(wc, fa.x, a0); a1 = fmaf(wc, fa.y, a1);
        a2 = fmaf(wc, fa.z, a2); a3 = fmaf(wc, fa.w, a3);
        b0 = fmaf(wc, fb.x, b0); b1 = fmaf(wc, fb.y, b1);
        b2 = fmaf(wc, fb.z, b2); b3 = fmaf(wc, fb.w, b3);
    }
    float4* frow = (float4*)(out_feat + (size_t)p * W_FEAT);
    frow[lane]      = make_float4(a0*vmask, a1*vmask, a2*vmask, a3*vmask);
    frow[lane + 32] = make_float4(b0*vmask, b1*vmask, b2*vmask, b3*vmask);
}

extern "C" void kernel_launch(void* const* d_in, const int* in_sizes, int n_in,
                              void* d_out, int out_size)
{
    const float* x  = (const float*)d_in[0];
    const float* gv = (const float*)d_in[1];
    const float* gf = (const float*)d_in[2];
    float* out = (float*)d_out;

    const int B = in_sizes[0] / 3;
    float* out_val  = out;        // [B]
    float* out_feat = out + B;    // [B, 256]

    if (B <= MAXB) {
        const int ppw = (B + WARPS_MAIN - 1) / WARPS_MAIN;
        histo_kernel<<<(B + 255) / 256, 256>>>(x, B);
        scan1_kernel<<<SCAN_BLOCKS, 1024>>>();
        scan2_kernel<<<1, SCAN_BLOCKS>>>();
        scatter_kernel<<<(B + 255) / 256, 256>>>(x, B);
        trilerp_main_kernel<<<GRID_MAIN, 128>>>(gv, gf, out_val, out_feat, B, ppw);
    } else {
        const int blocks = (B + 7) / 8;
        trilerp_kernel<<<blocks, 256>>>(x, gv, gf, out_val, out_feat, B);
    }
}

// round 11
// speedup vs baseline: 1.0087x; 1.0087x over previous
#include <cuda_runtime.h>
#include <stdint.h>

// VolGeoNet trilinear interp: Morton cell-sorted points, static (range,half)
// warp assignment, SMEM group-staged point loads, half-channel gather body.
// - Points counting-sorted by 18-bit Morton cell key (64^3 cells).
// - Warp w: range = w>>1 (contiguous ppw points), half = w&1 (128 channels).
//   Two warps (same CTA) cover one range -> per-point work split for latency
//   hiding; point math redundancy is cheap (issue not saturated).
// - Points staged 32 at a time: coalesced lane load -> SMEM -> LDS broadcast
//   (removes the per-iteration 250-600cy exposed g_xs latency).
// - 1776 CTAs x 128 thr, <=42 regs -> 12 CTAs/SM, 48 warps/SM, single wave.
// Inputs: x [B,3] f32, grid_value [65^3,1] f32, grid_feature [65^3,256] f32.
// Output: concat(out [B,1], feat [B,256]) float, out first.

#define N1 65
#define W_FEAT 256
#define MAXB 262144
#define NKEYS (64 * 64 * 64)
#define SCAN_BLOCKS 256           // NKEYS / 1024
#define GRID_MAIN 1776
#define NRANGES (GRID_MAIN * 2)   // 2 ranges per CTA (4 warps / 2 halves)

__device__ int    g_hist[NKEYS];      // zero at entry every call (scan1 resets)
__device__ int    g_binloc[NKEYS];
__device__ int    g_bsum[SCAN_BLOCKS];
__device__ int    g_bsumx[SCAN_BLOCKS];
__device__ int    g_key[MAXB];
__device__ int    g_rank[MAXB];
__device__ float4 g_xs[MAXB];         // sorted (x,y,z, bitcast point-index)

__device__ __forceinline__ uint32_t part1by2(uint32_t v)
{
    v &= 0x3FF;
    v = (v | (v << 16)) & 0x030000FF;
    v = (v | (v <<  8)) & 0x0300F00F;
    v = (v | (v <<  4)) & 0x030C30C3;
    v = (v | (v <<  2)) & 0x09249249;
    return v;
}

__global__ void histo_kernel(const float* __restrict__ x, int B)
{
    int p = blockIdx.x * blockDim.x + threadIdx.x;
    if (p >= B) return;
    const float rx = (x[p * 3 + 0] + 1.0f) * 32.0f;
    const float ry = (x[p * 3 + 1] + 1.0f) * 32.0f;
    const float rz = (x[p * 3 + 2] + 1.0f) * 32.0f;
    int ix = (int)floorf(rx); ix = ix < 0 ? 0 : (ix > 63 ? 63 : ix);
    int iy = (int)floorf(ry); iy = iy < 0 ? 0 : (iy > 63 ? 63 : iy);
    int iz = (int)floorf(rz); iz = iz < 0 ? 0 : (iz > 63 ? 63 : iz);
    const int key = (int)((part1by2(ix) << 2) | (part1by2(iy) << 1) | part1by2(iz));
    g_key[p] = key;
    g_rank[p] = atomicAdd(&g_hist[key], 1);
}

// Block-local exclusive scan over 1024 bins; emits block totals; resets g_hist.
__global__ void __launch_bounds__(1024) scan1_kernel()
{
    __shared__ int s[1024];
    const int t = threadIdx.x;
    const int idx = blockIdx.x * 1024 + t;
    const int v = g_hist[idx];
    s[t] = v;
    __syncthreads();
    for (int off = 1; off < 1024; off <<= 1) {
        int a = 0;
        if (t >= off) a = s[t - off];
        __syncthreads();
        if (t >= off) s[t] += a;
        __syncthreads();
    }
    g_binloc[idx] = s[t] - v;
    if (t == 1023) g_bsum[blockIdx.x] = s[t];
    g_hist[idx] = 0;                          // reset for next launch call
}

__global__ void __launch_bounds__(SCAN_BLOCKS) scan2_kernel()
{
    __shared__ int s[SCAN_BLOCKS];
    const int t = threadIdx.x;
    const int v = g_bsum[t];
    s[t] = v;
    __syncthreads();
    for (int off = 1; off < SCAN_BLOCKS; off <<= 1) {
        int a = 0;
        if (t >= off) a = s[t - off];
        __syncthreads();
        if (t >= off) s[t] += a;
        __syncthreads();
    }
    g_bsumx[t] = s[t] - v;
}

__global__ void scatter_kernel(const float* __restrict__ x, int B)
{
    int p = blockIdx.x * blockDim.x + threadIdx.x;
    if (p >= B) return;
    const int key = g_key[p];
    const int dst = g_binloc[key] + g_bsumx[key >> 10] + g_rank[p];
    g_xs[dst] = make_float4(x[p * 3 + 0], x[p * 3 + 1], x[p * 3 + 2],
                            __int_as_float(p));
}

// ──────────────────────────────────────────────────────────────────────────
// Main kernel.
__global__ void __launch_bounds__(128, 12) trilerp_main_kernel(
    const float* __restrict__ gv,
    const float* __restrict__ gf,
    float* __restrict__ out_val,   // [B]
    float* __restrict__ out_feat,  // [B, 256]
    int B, int ppw)
{
    __shared__ float4 s_pts[4][32];

    const int wid  = threadIdx.x >> 5;
    const int lane = threadIdx.x & 31;
    const int w = blockIdx.x * 4 + wid;
    const int range = w >> 1;
    const int half  = w & 1;

    int j0 = range * ppw;
    int jend = j0 + ppw;
    if (jend > B) jend = B;
    if (j0 >= jend) return;

    const int coff = (half << 5) + lane;   // float4 column within 1KB row

    // Prefetch first group into registers (coalesced).
    float4 cur = make_float4(0.f, 0.f, 0.f, 0.f);
    if (j0 + lane < jend) cur = __ldg(&g_xs[j0 + lane]);

    for (; j0 < jend; j0 += 32) {
        const int n = (jend - j0 < 32) ? (jend - j0) : 32;

        s_pts[wid][lane] = cur;
        __syncwarp();

        // Prefetch next group while processing this one.
        const int j1 = j0 + 32;
        if (j1 + lane < jend) cur = __ldg(&g_xs[j1 + lane]);

        for (int k = 0; k < n; k++) {
            const float4 xp = s_pts[wid][k];    // LDS broadcast
            const int p = __float_as_int(xp.w);

            const float rx = (xp.x + 1.0f) * 32.0f;
            const float ry = (xp.y + 1.0f) * 32.0f;
            const float rz = (xp.z + 1.0f) * 32.0f;

            const bool valid = (rx >= 0.0f) && (rx <= 64.0f) &&
                               (ry >= 0.0f) && (ry <= 64.0f) &&
                               (rz >= 0.0f) && (rz <= 64.0f);
            const float vmask = valid ? 1.0f : 0.0f;

            int ix = (int)floorf(rx); ix = ix < 0 ? 0 : (ix > 63 ? 63 : ix);
            int iy = (int)floorf(ry); iy = iy < 0 ? 0 : (iy > 63 ? 63 : iy);
            int iz = (int)floorf(rz); iz = iz < 0 ? 0 : (iz > 63 ? 63 : iz);

            const float tx = rx - (float)ix;
            const float ty = ry - (float)iy;
            const float tz = rz - (float)iz;
            const float wx0 = 1.0f - tx, wy0 = 1.0f - ty, wz0 = 1.0f - tz;

            const float wyz0 = wy0 * wz0;
            const float wyz1 = wy0 * tz;
            const float wyz2 = ty  * wz0;
            const float wyz3 = ty  * tz;

            const int base = (ix * N1 + iy) * N1 + iz;
            const float4* rlo = (const float4*)gf + (size_t)base * (W_FEAT / 4) + coff;
            const float4* rhi = rlo + (size_t)(N1 * N1) * (W_FEAT / 4);

            // x-low plane (4 batched loads)
            const float4 f0 = __ldg(rlo);
            const float4 f1 = __ldg(rlo + (W_FEAT / 4));
            const float4 f2 = __ldg(rlo + N1 * (W_FEAT / 4));
            const float4 f3 = __ldg(rlo + (N1 + 1) * (W_FEAT / 4));
            float s0, s1, s2, s3;
            s0 = wyz0 * f0.x; s1 = wyz0 * f0.y; s2 = wyz0 * f0.z; s3 = wyz0 * f0.w;
            s0 = fmaf(wyz1, f1.x, s0); s1 = fmaf(wyz1, f1.y, s1);
            s2 = fmaf(wyz1, f1.z, s2); s3 = fmaf(wyz1, f1.w, s3);
            s0 = fmaf(wyz2, f2.x, s0); s1 = fmaf(wyz2, f2.y, s1);
            s2 = fmaf(wyz2, f2.z, s2); s3 = fmaf(wyz2, f2.w, s3);
            s0 = fmaf(wyz3, f3.x, s0); s1 = fmaf(wyz3, f3.y, s1);
            s2 = fmaf(wyz3, f3.z, s2); s3 = fmaf(wyz3, f3.w, s3);
            s0 *= wx0; s1 *= wx0; s2 *= wx0; s3 *= wx0;

            // x-high plane (4 batched loads)
            const float4 g0 = __ldg(rhi);
            const float4 g1 = __ldg(rhi + (W_FEAT / 4));
            const float4 g2 = __ldg(rhi + N1 * (W_FEAT / 4));
            const float4 g3 = __ldg(rhi + (N1 + 1) * (W_FEAT / 4));
            float u0, u1, u2, u3;
            u0 = wyz0 * g0.x; u1 = wyz0 * g0.y; u2 = wyz0 * g0.z; u3 = wyz0 * g0.w;
            u0 = fmaf(wyz1, g1.x, u0); u1 = fmaf(wyz1, g1.y, u1);
            u2 = fmaf(wyz1, g1.z, u2); u3 = fmaf(wyz1, g1.w, u3);
            u0 = fmaf(wyz2, g2.x, u0); u1 = fmaf(wyz2, g2.y, u1);
            u2 = fmaf(wyz2, g2.z, u2); u3 = fmaf(wyz2, g2.w, u3);
            u0 = fmaf(wyz3, g3.x, u0); u1 = fmaf(wyz3, g3.y, u1);
            u2 = fmaf(wyz3, g3.z, u2); u3 = fmaf(wyz3, g3.w, u3);

            s0 = fmaf(tx, u0, s0); s1 = fmaf(tx, u1, s1);
            s2 = fmaf(tx, u2, s2); s3 = fmaf(tx, u3, s3);

            float4* frow = (float4*)(out_feat + (size_t)p * W_FEAT);
            __stcs(frow + coff,
                   make_float4(s0 * vmask, s1 * vmask, s2 * vmask, s3 * vmask));

            if (half == 0) {
                // grid_value: lanes 0..7 own one corner.
                const float wxs = (lane & 4) ? tx : wx0;
                const float wys = (lane & 2) ? ty : wy0;
                const float wzs = (lane & 1) ? tz : wz0;
                const int off = ((lane & 4) ? N1 * N1 : 0) +
                                ((lane & 2) ? N1 : 0) + (lane & 1);
                float gvv = 0.0f;
                if (lane < 8) gvv = wxs * wys * wzs * __ldg(gv + base + off);
                gvv += __shfl_xor_sync(0xffffffffu, gvv, 4);
                gvv += __shfl_xor_sync(0xffffffffu, gvv, 2);
                gvv += __shfl_xor_sync(0xffffffffu, gvv, 1);
                if (lane == 0) out_val[p] = gvv * vmask;
            }
        }
        __syncwarp();
    }
}

// Fallback (B > MAXB): direct global-gather version, unsorted.
__global__ void __launch_bounds__(256) trilerp_kernel(
    const float* __restrict__ x,
    const float* __restrict__ gv,
    const float* __restrict__ gf,
    float* __restrict__ out_val,
    float* __restrict__ out_feat,
    int B)
{
    const int p = (blockIdx.x * blockDim.x + threadIdx.x) >> 5;
    const int lane = threadIdx.x & 31;
    if (p >= B) return;

    const float rx = (__ldg(x + p * 3 + 0) + 1.0f) * 32.0f;
    const float ry = (__ldg(x + p * 3 + 1) + 1.0f) * 32.0f;
    const float rz = (__ldg(x + p * 3 + 2) + 1.0f) * 32.0f;
    const bool valid = (rx >= 0.0f) && (rx <= 64.0f) && (ry >= 0.0f) &&
                       (ry <= 64.0f) && (rz >= 0.0f) && (rz <= 64.0f);
    const float vmask = valid ? 1.0f : 0.0f;
    int ix = (int)floorf(rx); ix = ix < 0 ? 0 : (ix > 63 ? 63 : ix);
    int iy = (int)floorf(ry); iy = iy < 0 ? 0 : (iy > 63 ? 63 : iy);
    int iz = (int)floorf(rz); iz = iz < 0 ? 0 : (iz > 63 ? 63 : iz);
    const float tx = rx - ix, ty = ry - iy, tz = rz - iz;
    const int base = (ix * N1 + iy) * N1 + iz;
    const float wx0 = 1.0f - tx, wy0 = 1.0f - ty, wz0 = 1.0f - tz;
    float w[8] = { wx0*wy0*wz0, wx0*wy0*tz, wx0*ty*wz0, wx0*ty*tz,
                   tx*wy0*wz0,  tx*wy0*tz,  tx*ty*wz0,  tx*ty*tz };
    const int offs[8] = { 0, 1, N1, N1+1, N1*N1, N1*N1+1, N1*N1+N1, N1*N1+N1+1 };

    float gvv = 0.0f;
    if (lane < 8) gvv = w[lane] * __ldg(gv + base + offs[lane]);
    gvv += __shfl_xor_sync(0xffffffffu, gvv, 4);
    gvv += __shfl_xor_sync(0xffffffffu, gvv, 2);
    gvv += __shfl_xor_sync(0xffffffffu, gvv, 1);
    if (lane == 0) out_val[p] = gvv * vmask;

    float a0=0,a1=0,a2=0,a3=0,b0=0,b1=0,b2=0,b3=0;
#pragma unroll
    for (int c = 0; c < 8; c++) {
        const float4* row = (const float4*)(gf + (size_t)(base + offs[c]) * W_FEAT);
        const float4 fa = __ldg(row + lane);
        const float4 fb = __ldg(row + lane + 32);
        const float wc = w[c];
        a0 = fmaf(wc, fa.x, a0); a1 = fmaf(wc, fa.y, a1);
        a2 = fmaf(wc, fa.z, a2); a3 = fmaf(wc, fa.w, a3);
        b0 = fmaf(wc, fb.x, b0); b1 = fmaf(wc, fb.y, b1);
        b2 = fmaf(wc, fb.z, b2); b3 = fmaf(wc, fb.w, b3);
    }
    float4* frow = (float4*)(out_feat + (size_t)p * W_FEAT);
    frow[lane]      = make_float4(a0*vmask, a1*vmask, a2*vmask, a3*vmask);
    frow[lane + 32] = make_float4(b0*vmask, b1*vmask, b2*vmask, b3*vmask);
}

extern "C" void kernel_launch(void* const* d_in, const int* in_sizes, int n_in,
                              void* d_out, int out_size)
{
    const float* x  = (const float*)d_in[0];
    const float* gv = (const float*)d_in[1];
    const float* gf = (const float*)d_in[2];
    float* out = (float*)d_out;

    const int B = in_sizes[0] / 3;
    float* out_val  = out;        // [B]
    float* out_feat = out + B;    // [B, 256]

    if (B <= MAXB) {
        const int ppw = (B + NRANGES - 1) / NRANGES;
        histo_kernel<<<(B + 255) / 256, 256>>>(x, B);
        scan1_kernel<<<SCAN_BLOCKS, 1024>>>();
        scan2_kernel<<<1, SCAN_BLOCKS>>>();
        scatter_kernel<<<(B + 255) / 256, 256>>>(x, B);
        trilerp_main_kernel<<<GRID_MAIN, 128>>>(gv, gf, out_val, out_feat, B, ppw);
    } else {
        const int blocks = (B + 7) / 8;
        trilerp_kernel<<<blocks, 256>>>(x, gv, gf, out_val, out_feat, B);
    }
}

// round 13
// speedup vs baseline: 1.1485x; 1.1386x over previous
#include <cuda_runtime.h>
#include <stdint.h>

// VolGeoNet trilinear interp: cell-resolved counting sort + per-cell corner
// row reuse. R9 skeleton (work item = (half, 4^3 region), work stealing,
// 4 warps/CTA on the same region) but gather rows are loaded ONCE per
// non-empty cell and reused for all points in that cell (~1.6x fewer LDGs).
// Inputs: x [B,3] f32, grid_value [65^3,1] f32, grid_feature [65^3,256] f32.
// Output: concat(out [B,1], feat [B,256]) float, out first.

#define N1 65
#define W_FEAT 256
#define MAXB 262144
#define NREGIONS 4096             // 16^3 regions of 4^3 cells
#define NKEYS (NREGIONS * 64)     // 262144 cells, region-major
#define SCAN_BLOCKS 256           // NKEYS / 1024
#define NITEMS (2 * NREGIONS)
#define GRID_MAIN 1480            // 10 CTAs/SM

__device__ int    g_hist[NKEYS];      // zero at entry every call (scan1 resets)
__device__ int    g_binstart[NKEYS + 1];
__device__ int    g_bsum[SCAN_BLOCKS];
__device__ int    g_bsumx[SCAN_BLOCKS];
__device__ int    g_keyarr[MAXB];
__device__ int    g_rank[MAXB];
__device__ float4 g_xs[MAXB];         // sorted (x,y,z, bitcast point-index)
__device__ int    g_item;             // work-stealing cursor (reset by histo)

__device__ __forceinline__ int cell_key(int ix, int iy, int iz)
{
    const int region = ((ix >> 2) << 8) | ((iy >> 2) << 4) | (iz >> 2);
    const int cig    = ((ix & 3) << 4) | ((iy & 3) << 2) | (iz & 3);
    return (region << 6) | cig;
}

__global__ void histo_kernel(const float* __restrict__ x, int B)
{
    int p = blockIdx.x * blockDim.x + threadIdx.x;
    if (p == 0) g_item = 0;
    if (p >= B) return;
    const float rx = (x[p * 3 + 0] + 1.0f) * 32.0f;
    const float ry = (x[p * 3 + 1] + 1.0f) * 32.0f;
    const float rz = (x[p * 3 + 2] + 1.0f) * 32.0f;
    int ix = (int)floorf(rx); ix = ix < 0 ? 0 : (ix > 63 ? 63 : ix);
    int iy = (int)floorf(ry); iy = iy < 0 ? 0 : (iy > 63 ? 63 : iy);
    int iz = (int)floorf(rz); iz = iz < 0 ? 0 : (iz > 63 ? 63 : iz);
    const int key = cell_key(ix, iy, iz);
    g_keyarr[p] = key;
    g_rank[p] = atomicAdd(&g_hist[key], 1);
}

// Block-local exclusive scan over 1024 bins; emits block totals; resets g_hist.
__global__ void __launch_bounds__(1024) scan1_kernel()
{
    __shared__ int s[1024];
    const int t = threadIdx.x;
    const int idx = blockIdx.x * 1024 + t;
    const int v = g_hist[idx];
    s[t] = v;
    __syncthreads();
    for (int off = 1; off < 1024; off <<= 1) {
        int a = 0;
        if (t >= off) a = s[t - off];
        __syncthreads();
        if (t >= off) s[t] += a;
        __syncthreads();
    }
    g_binstart[idx] = s[t] - v;   // block-local exclusive; globalized in scan2/scatter
    if (t == 1023) g_bsum[blockIdx.x] = s[t];
    g_hist[idx] = 0;
}

// Exclusive-scan the 256 block totals, then scatter adds them in. Also fix up
// g_binstart into fully-global offsets here (one pass, 256 blocks of 1024).
__global__ void __launch_bounds__(SCAN_BLOCKS) scan2_kernel(int B)
{
    __shared__ int s[SCAN_BLOCKS];
    const int t = threadIdx.x;
    const int v = g_bsum[t];
    s[t] = v;
    __syncthreads();
    for (int off = 1; off < SCAN_BLOCKS; off <<= 1) {
        int a = 0;
        if (t >= off) a = s[t - off];
        __syncthreads();
        if (t >= off) s[t] += a;
        __syncthreads();
    }
    g_bsumx[t] = s[t] - v;
    if (t == SCAN_BLOCKS - 1) g_binstart[NKEYS] = B;
}

// Globalize binstart (add block prefix) — separate pass over 262144 entries.
__global__ void __launch_bounds__(1024) fixup_kernel()
{
    const int idx = blockIdx.x * 1024 + threadIdx.x;
    g_binstart[idx] += g_bsumx[idx >> 10];
}

__global__ void scatter_kernel(const float* __restrict__ x, int B)
{
    int p = blockIdx.x * blockDim.x + threadIdx.x;
    if (p >= B) return;
    const int key = g_keyarr[p];
    const int dst = g_binstart[key] + g_rank[p];
    g_xs[dst] = make_float4(x[p * 3 + 0], x[p * 3 + 1], x[p * 3 + 2],
                            __int_as_float(p));
}

// ──────────────────────────────────────────────────────────────────────────
// Main kernel: work item = (half, region). 4 warps of the CTA stride over the
// region's 64 cells; per non-empty cell the 8 corner rows (and 8 gv scalars)
// are loaded once and reused for every point in the cell.
__global__ void __launch_bounds__(128, 10) trilerp_main_kernel(
    const float* __restrict__ gv,
    const float* __restrict__ gf,
    float* __restrict__ out_val,   // [B]
    float* __restrict__ out_feat)  // [B, 256]
{
    __shared__ int s_item;
    const int tid  = threadIdx.x;
    const int wid  = tid >> 5;
    const int lane = tid & 31;

    for (;;) {
        if (tid == 0) s_item = atomicAdd(&g_item, 1);
        __syncthreads();
        const int item = s_item;
        __syncthreads();
        if (item >= NITEMS) return;

        const int half   = item >> 12;
        const int region = item & (NREGIONS - 1);
        const int rx0 = ((region >> 8) & 15) << 2;
        const int ry0 = ((region >> 4) & 15) << 2;
        const int rz0 = (region & 15) << 2;

        const int coff = (half << 5) + lane;   // float4 column within 1KB row
        const int keybase = region << 6;

        for (int cig = wid; cig < 64; cig += 4) {
            const int cstart = g_binstart[keybase + cig];
            const int cend   = g_binstart[keybase + cig + 1];
            if (cstart == cend) continue;

            const int ix = rx0 + (cig >> 4);
            const int iy = ry0 + ((cig >> 2) & 3);
            const int iz = rz0 + (cig & 3);
            const int base = (ix * N1 + iy) * N1 + iz;

            // Load 8 corner rows once for this cell.
            const float4* r = (const float4*)gf + (size_t)base * (W_FEAT / 4) + coff;
            const float4 f0 = __ldg(r);
            const float4 f1 = __ldg(r + (W_FEAT / 4));
            const float4 f2 = __ldg(r + N1 * (W_FEAT / 4));
            const float4 f3 = __ldg(r + (N1 + 1) * (W_FEAT / 4));
            const float4* rh = r + N1 * N1 * (W_FEAT / 4);
            const float4 f4 = __ldg(rh);
            const float4 f5 = __ldg(rh + (W_FEAT / 4));
            const float4 f6 = __ldg(rh + N1 * (W_FEAT / 4));
            const float4 f7 = __ldg(rh + (N1 + 1) * (W_FEAT / 4));

            // gv corner value for lanes 0..7 (half 0 only uses it).
            float gvrow = 0.0f;
            if (half == 0 && lane < 8) {
                const int off = ((lane & 4) ? N1 * N1 : 0) +
                                ((lane & 2) ? N1 : 0) + (lane & 1);
                gvrow = __ldg(gv + base + off);
            }

            for (int j = cstart; j < cend; j++) {
                const float4 xp = __ldg(&g_xs[j]);
                const int p = __float_as_int(xp.w);

                const float rx = (xp.x + 1.0f) * 32.0f;
                const float ry = (xp.y + 1.0f) * 32.0f;
                const float rz = (xp.z + 1.0f) * 32.0f;

                const bool valid = (rx >= 0.0f) && (rx <= 64.0f) &&
                                   (ry >= 0.0f) && (ry <= 64.0f) &&
                                   (rz >= 0.0f) && (rz <= 64.0f);
                const float vmask = valid ? 1.0f : 0.0f;

                const float tx = rx - (float)ix;
                const float ty = ry - (float)iy;
                const float tz = rz - (float)iz;
                const float wx0 = 1.0f - tx, wy0 = 1.0f - ty, wz0 = 1.0f - tz;

                const float w0 = wx0 * wy0 * wz0;
                const float w1 = wx0 * wy0 * tz;
                const float w2 = wx0 * ty  * wz0;
                const float w3 = wx0 * ty  * tz;
                const float w4 = tx  * wy0 * wz0;
                const float w5 = tx  * wy0 * tz;
                const float w6 = tx  * ty  * wz0;
                const float w7 = tx  * ty  * tz;

                float s0, s1, s2, s3;
                s0 = w0 * f0.x; s1 = w0 * f0.y; s2 = w0 * f0.z; s3 = w0 * f0.w;
                s0 = fmaf(w1, f1.x, s0); s1 = fmaf(w1, f1.y, s1);
                s2 = fmaf(w1, f1.z, s2); s3 = fmaf(w1, f1.w, s3);
                s0 = fmaf(w2, f2.x, s0); s1 = fmaf(w2, f2.y, s1);
                s2 = fmaf(w2, f2.z, s2); s3 = fmaf(w2, f2.w, s3);
                s0 = fmaf(w3, f3.x, s0); s1 = fmaf(w3, f3.y, s1);
                s2 = fmaf(w3, f3.z, s2); s3 = fmaf(w3, f3.w, s3);
                s0 = fmaf(w4, f4.x, s0); s1 = fmaf(w4, f4.y, s1);
                s2 = fmaf(w4, f4.z, s2); s3 = fmaf(w4, f4.w, s3);
                s0 = fmaf(w5, f5.x, s0); s1 = fmaf(w5, f5.y, s1);
                s2 = fmaf(w5, f5.z, s2); s3 = fmaf(w5, f5.w, s3);
                s0 = fmaf(w6, f6.x, s0); s1 = fmaf(w6, f6.y, s1);
                s2 = fmaf(w6, f6.z, s2); s3 = fmaf(w6, f6.w, s3);
                s0 = fmaf(w7, f7.x, s0); s1 = fmaf(w7, f7.y, s1);
                s2 = fmaf(w7, f7.z, s2); s3 = fmaf(w7, f7.w, s3);

                float4* frow = (float4*)(out_feat + (size_t)p * W_FEAT);
                __stcs(frow + coff,
                       make_float4(s0 * vmask, s1 * vmask, s2 * vmask, s3 * vmask));

                if (half == 0) {
                    const float wxs = (lane & 4) ? tx : wx0;
                    const float wys = (lane & 2) ? ty : wy0;
                    const float wzs = (lane & 1) ? tz : wz0;
                    float gvv = (lane < 8) ? wxs * wys * wzs * gvrow : 0.0f;
                    gvv += __shfl_xor_sync(0xffffffffu, gvv, 4);
                    gvv += __shfl_xor_sync(0xffffffffu, gvv, 2);
                    gvv += __shfl_xor_sync(0xffffffffu, gvv, 1);
                    if (lane == 0) out_val[p] = gvv * vmask;
                }
            }
        }
    }
}

// Fallback (B > MAXB): direct global-gather version, unsorted.
__global__ void __launch_bounds__(256) trilerp_kernel(
    const float* __restrict__ x,
    const float* __restrict__ gv,
    const float* __restrict__ gf,
    float* __restrict__ out_val,
    float* __restrict__ out_feat,
    int B)
{
    const int p = (blockIdx.x * blockDim.x + threadIdx.x) >> 5;
    const int lane = threadIdx.x & 31;
    if (p >= B) return;

    const float rx = (__ldg(x + p * 3 + 0) + 1.0f) * 32.0f;
    const float ry = (__ldg(x + p * 3 + 1) + 1.0f) * 32.0f;
    const float rz = (__ldg(x + p * 3 + 2) + 1.0f) * 32.0f;
    const bool valid = (rx >= 0.0f) && (rx <= 64.0f) && (ry >= 0.0f) &&
                       (ry <= 64.0f) && (rz >= 0.0f) && (rz <= 64.0f);
    const float vmask = valid ? 1.0f : 0.0f;
    int ix = (int)floorf(rx); ix = ix < 0 ? 0 : (ix > 63 ? 63 : ix);
    int iy = (int)floorf(ry); iy = iy < 0 ? 0 : (iy > 63 ? 63 : iy);
    int iz = (int)floorf(rz); iz = iz < 0 ? 0 : (iz > 63 ? 63 : iz);
    const float tx = rx - ix, ty = ry - iy, tz = rz - iz;
    const int base = (ix * N1 + iy) * N1 + iz;
    const float wx0 = 1.0f - tx, wy0 = 1.0f - ty, wz0 = 1.0f - tz;
    float w[8] = { wx0*wy0*wz0, wx0*wy0*tz, wx0*ty*wz0, wx0*ty*tz,
                   tx*wy0*wz0,  tx*wy0*tz,  tx*ty*wz0,  tx*ty*tz };
    const int offs[8] = { 0, 1, N1, N1+1, N1*N1, N1*N1+1, N1*N1+N1, N1*N1+N1+1 };

    float gvv = 0.0f;
    if (lane < 8) gvv = w[lane] * __ldg(gv + base + offs[lane]);
    gvv += __shfl_xor_sync(0xffffffffu, gvv, 4);
    gvv += __shfl_xor_sync(0xffffffffu, gvv, 2);
    gvv += __shfl_xor_sync(0xffffffffu, gvv, 1);
    if (lane == 0) out_val[p] = gvv * vmask;

    float a0=0,a1=0,a2=0,a3=0,b0=0,b1=0,b2=0,b3=0;
#pragma unroll
    for (int c = 0; c < 8; c++) {
        const float4* row = (const float4*)(gf + (size_t)(base + offs[c]) * W_FEAT);
        const float4 fa = __ldg(row + lane);
        const float4 fb = __ldg(row + lane + 32);
        const float wc = w[c];
        a0 = fmaf(wc, fa.x, a0); a1 = fmaf(wc, fa.y, a1);
        a2 = fmaf(wc, fa.z, a2); a3 = fmaf(wc, fa.w, a3);
        b0 = fmaf(wc, fb.x, b0); b1 = fmaf(wc, fb.y, b1);
        b2 = fmaf(wc, fb.z, b2); b3 = fmaf(wc, fb.w, b3);
    }
    float4* frow = (float4*)(out_feat + (size_t)p * W_FEAT);
    frow[lane]      = make_float4(a0*vmask, a1*vmask, a2*vmask, a3*vmask);
    frow[lane + 32] = make_float4(b0*vmask, b1*vmask, b2*vmask, b3*vmask);
}

extern "C" void kernel_launch(void* const* d_in, const int* in_sizes, int n_in,
                              void* d_out, int out_size)
{
    const float* x  = (const float*)d_in[0];
    const float* gv = (const float*)d_in[1];
    const float* gf = (const float*)d_in[2];
    float* out = (float*)d_out;

    const int B = in_sizes[0] / 3;
    float* out_val  = out;        // [B]
    float* out_feat = out + B;    // [B, 256]

    if (B <= MAXB) {
        histo_kernel<<<(B + 255) / 256, 256>>>(x, B);
        scan1_kernel<<<SCAN_BLOCKS, 1024>>>();
        scan2_kernel<<<1, SCAN_BLOCKS>>>(B);
        fixup_kernel<<<SCAN_BLOCKS, 1024>>>();
        scatter_kernel<<<(B + 255) / 256, 256>>>(x, B);
        trilerp_main_kernel<<<GRID_MAIN, 128>>>(gv, gf, out_val, out_feat);
    } else {
        const int blocks = (B + 7) / 8;
        trilerp_kernel<<<blocks, 256>>>(x, gv, gf, out_val, out_feat, B);
    }
}